// round 3
// baseline (speedup 1.0000x reference)
#include <cuda_runtime.h>
#include <math.h>

#define NN 100000
#define NE 1600000
#define NG 256
#define FIN 12
#define HID 64
#define FCD 140
#define SPLIT 8
#define SCAN_T 1024
#define CHUNK  98   // 1024*98 = 100352 >= NN

// Scratch (static __device__ — no allocation allowed)
__device__ __align__(16) float g_g1[NN * HID];
__device__ __align__(16) float g_agg1[NN * HID];
__device__ __align__(16) float g_g2[NN * HID];
__device__ __align__(16) float g_agg2[NN * HID];
__device__ float g_dinv[NN];
__device__ int   g_cnt[NN];          // in-degree (no self loop)
__device__ int   g_rowst[NN + 1];    // CSR row start
__device__ int   g_rowcur[NN];       // fill cursors
__device__ int   g_csrc[NE];         // CSR src ids
__device__ float g_pooled[NG * FCD];

// ---------------------------------------------------------------------------
// K0: per-launch re-init: cnt=0, pooled=0
__global__ void k_init() {
    int i = blockIdx.x * blockDim.x + threadIdx.x;
    if (i < NN) g_cnt[i] = 0;
    if (i < NG * FCD) g_pooled[i] = 0.0f;
}

// K1: in-degree over dst (edge_index row 1)
__global__ void k_deg(const int* __restrict__ ei) {
    int e = blockIdx.x * blockDim.x + threadIdx.x;
    if (e < NE) atomicAdd(&g_cnt[ei[NE + e]], 1);
}

// K2: single-block scan: rowst/rowcur = exclusive prefix of cnt; dinv = rsqrt(cnt+1)
__global__ void k_scan() {
    __shared__ float ssum[SCAN_T];
    int t = threadIdx.x;
    int base = t * CHUNK;
    int lim = min(base + CHUNK, NN);
    int s = 0;
    for (int i = base; i < lim; i++) s += g_cnt[i];
    ssum[t] = (float)s;  // counts fit fp32 exactly? NE=1.6M < 2^24, yes
    __syncthreads();
    // Hillis-Steele inclusive scan on ints stored as float (exact, < 2^24)
    for (int off = 1; off < SCAN_T; off <<= 1) {
        float v = ssum[t];
        float u = (t >= off) ? ssum[t - off] : 0.0f;
        __syncthreads();
        ssum[t] = v + u;
        __syncthreads();
    }
    int run = (int)ssum[t] - s;  // exclusive prefix for this chunk
    for (int i = base; i < lim; i++) {
        int c = g_cnt[i];
        g_rowst[i]  = run;
        g_rowcur[i] = run;
        g_dinv[i]   = rsqrtf((float)(c + 1));
        run += c;
    }
    if (t == SCAN_T - 1) g_rowst[NN] = NE;
}

// K3: CSR fill
__global__ void k_fill(const int* __restrict__ ei) {
    int e = blockIdx.x * blockDim.x + threadIdx.x;
    if (e >= NE) return;
    int src = ei[e];
    int dst = ei[NE + e];
    int pos = atomicAdd(&g_rowcur[dst], 1);
    g_csrc[pos] = src;
}

// K4: g1 = dinv * (x @ W1). 16 threads/node, float4 outputs.
__global__ void k_xw1(const float* __restrict__ x, const float* __restrict__ W1) {
    __shared__ float4 sW[FIN * 16];
    for (int i = threadIdx.x; i < FIN * 16; i += blockDim.x)
        sW[i] = ((const float4*)W1)[i];
    __syncthreads();
    int gid = blockIdx.x * blockDim.x + threadIdx.x;
    int node = gid >> 4;
    if (node >= NN) return;
    int c = gid & 15;
    const float* xr = x + node * FIN;
    float4 a = make_float4(0.f, 0.f, 0.f, 0.f);
#pragma unroll
    for (int k = 0; k < FIN; k++) {
        float xk = __ldg(xr + k);
        float4 w = sW[k * 16 + c];
        a.x += xk * w.x; a.y += xk * w.y; a.z += xk * w.z; a.w += xk * w.w;
    }
    float d = g_dinv[node];
    a.x *= d; a.y *= d; a.z *= d; a.w *= d;
    ((float4*)g_g1)[node * 16 + c] = a;
}

// K5/K7: CSR gather-aggregate: agg[i] = g[i] + sum_{j->i} g[j]
__global__ void k_agg(int layer) {
    int gid = blockIdx.x * blockDim.x + threadIdx.x;
    int node = gid >> 4;
    if (node >= NN) return;
    int c = gid & 15;
    const float4* g   = layer ? (const float4*)g_g2   : (const float4*)g_g1;
    float4*       agg = layer ? (float4*)g_agg2       : (float4*)g_agg1;
    int beg = g_rowst[node];
    int end = g_rowst[node + 1];
    float4 acc = g[node * 16 + c];  // self-loop term
    int j = beg;
    for (; j + 1 < end; j += 2) {
        int s0 = g_csrc[j];
        int s1 = g_csrc[j + 1];
        float4 v0 = g[s0 * 16 + c];
        float4 v1 = g[s1 * 16 + c];
        acc.x += v0.x; acc.y += v0.y; acc.z += v0.z; acc.w += v0.w;
        acc.x += v1.x; acc.y += v1.y; acc.z += v1.z; acc.w += v1.w;
    }
    if (j < end) {
        int s0 = g_csrc[j];
        float4 v0 = g[s0 * 16 + c];
        acc.x += v0.x; acc.y += v0.y; acc.z += v0.z; acc.w += v0.w;
    }
    agg[node * 16 + c] = acc;
}

// K6: h1 = tanh(dinv*agg1 + b1) (kept in smem); g2 = dinv * (h1 @ W2).
__global__ void k_l2(const float* __restrict__ W2, const float* __restrict__ b1) {
    __shared__ float sW[HID * HID];   // 16 KB
    __shared__ float sh[32 * HID];    // 8 KB
    int tid = threadIdx.x;
    for (int i = tid; i < HID * HID; i += 256) sW[i] = W2[i];
    int n0 = blockIdx.x * 32;
    for (int i = tid; i < 32 * HID; i += 256) {
        int node = n0 + (i >> 6);
        int f    = i & 63;
        sh[i] = tanhf(g_dinv[node] * g_agg1[node * HID + f] + b1[f]);
    }
    __syncthreads();
    for (int i = tid; i < 32 * HID; i += 256) {
        int ln = i >> 6;
        int f  = i & 63;
        const float* hr = sh + ln * HID;
        float s = 0.0f;
#pragma unroll 8
        for (int k = 0; k < HID; k++) s += hr[k] * sW[k * HID + f];
        int node = n0 + ln;
        g_g2[node * HID + f] = g_dinv[node] * s;
    }
}

// K8: pooling. batch sorted -> block per (graph, split); lane per feature.
__global__ void k_pool(const float* __restrict__ x,
                       const float* __restrict__ b1,
                       const float* __restrict__ b2,
                       const int* __restrict__ batch) {
    int g = blockIdx.x / SPLIT;
    int s = blockIdx.x % SPLIT;
    int f = threadIdx.x;

    int a = 0, b = NN;
    while (a < b) { int m = (a + b) >> 1; if (batch[m] < g) a = m + 1; else b = m; }
    int lo = a;
    a = lo; b = NN;
    while (a < b) { int m = (a + b) >> 1; if (batch[m] < g + 1) a = m + 1; else b = m; }
    int hi = a;

    int cnt = hi - lo;
    int per = (cnt + SPLIT - 1) / SPLIT;
    int st  = lo + s * per;
    int en  = min(st + per, hi);

    if (f < FCD) {
        float acc = 0.0f;
        for (int node = st; node < en; node++) {
            float v;
            if (f < FIN) {
                v = x[node * FIN + f];
            } else if (f < FIN + HID) {
                int k = f - FIN;
                v = tanhf(g_dinv[node] * g_agg1[node * HID + k] + b1[k]);
            } else {
                int k = f - FIN - HID;
                v = tanhf(g_dinv[node] * g_agg2[node * HID + k] + b2[k]);
            }
            acc += v;
        }
        if (st < en) atomicAdd(&g_pooled[g * FCD + f], acc);
    }
}

// K9: out[g,o] = sum_k pooled[g,k] * fc_W[o,k] + fc_b[o]
__global__ void k_fc(const float* __restrict__ fcW,
                     const float* __restrict__ fcb,
                     float* __restrict__ out) {
    __shared__ float sp[FCD];
    int g = blockIdx.x;
    for (int i = threadIdx.x; i < FCD; i += blockDim.x) sp[i] = g_pooled[g * FCD + i];
    __syncthreads();
    int o = threadIdx.x;
    if (o < FCD) {
        const float* wr = fcW + o * FCD;
        float s = fcb[o];
        for (int k = 0; k < FCD; k++) s += sp[k] * wr[k];
        out[g * FCD + o] = s;
    }
}

// ---------------------------------------------------------------------------
extern "C" void kernel_launch(void* const* d_in, const int* in_sizes, int n_in,
                              void* d_out, int out_size) {
    const float* x    = (const float*)d_in[0];
    const float* W1   = (const float*)d_in[1];
    const float* b1   = (const float*)d_in[2];
    const float* W2   = (const float*)d_in[3];
    const float* b2   = (const float*)d_in[4];
    const float* fcW  = (const float*)d_in[5];
    const float* fcb  = (const float*)d_in[6];
    const int*   ei   = (const int*)d_in[7];     // int32
    const int*   batch= (const int*)d_in[8];     // int32
    float* out = (float*)d_out;
    (void)in_sizes; (void)n_in; (void)out_size;

    k_init<<<(NN + 255) / 256, 256>>>();
    k_deg <<<(NE + 255) / 256, 256>>>(ei);
    k_scan<<<1, SCAN_T>>>();
    k_fill<<<(NE + 255) / 256, 256>>>(ei);
    k_xw1 <<<(NN * 16 + 255) / 256, 256>>>(x, W1);
    k_agg <<<(NN * 16 + 255) / 256, 256>>>(0);
    k_l2  <<<(NN + 31) / 32, 256>>>(W2, b1);
    k_agg <<<(NN * 16 + 255) / 256, 256>>>(1);
    k_pool<<<NG * SPLIT, 160>>>(x, b1, b2, batch);
    k_fc  <<<NG, 160>>>(fcW, fcb, out);
}

// round 5
// speedup vs baseline: 1.7311x; 1.7311x over previous
#include <cuda_runtime.h>
#include <math.h>

#define NN 100000
#define NE 1600000
#define NG 256
#define FIN 12
#define HID 64
#define FCD 140
#define SPLIT 8
#define NB 391          // 391*256 = 100096 >= NN

// Scratch (static __device__ — no allocation allowed)
__device__ __align__(16) float g_g1[NN * HID];
__device__ __align__(16) float g_agg1[NN * HID];
__device__ __align__(16) float g_g2[NN * HID];
__device__ __align__(16) float g_agg2[NN * HID];
__device__ float g_dinv[NN];
__device__ int   g_cnt[NN];          // in-degree (no self loop)
__device__ int   g_rowst[NN + 1];    // CSR row start
__device__ int   g_rowcur[NN];       // fill cursors
__device__ int   g_csrc[NE];         // CSR src ids
__device__ int   g_bsum[NB];         // per-block degree sums
__device__ int   g_boff[NB];         // exclusive prefix of block sums
__device__ float g_pooled[NG * FCD];

// ---------------------------------------------------------------------------
// K0: per-launch re-init: cnt=0, pooled=0
__global__ void k_init() {
    int i = blockIdx.x * blockDim.x + threadIdx.x;
    if (i < NN) g_cnt[i] = 0;
    if (i < NG * FCD) g_pooled[i] = 0.0f;
}

// K1: in-degree over dst (edge_index row 1)
__global__ void k_deg(const int* __restrict__ ei) {
    int e = blockIdx.x * blockDim.x + threadIdx.x;
    if (e < NE) atomicAdd(&g_cnt[ei[NE + e]], 1);
}

// K2a: coalesced per-block sums of cnt
__global__ void k_scan1() {
    __shared__ int sred[8];
    int b = blockIdx.x, t = threadIdx.x;
    int i = b * 256 + t;
    int v = (i < NN) ? g_cnt[i] : 0;
#pragma unroll
    for (int o = 16; o > 0; o >>= 1) v += __shfl_down_sync(0xffffffffu, v, o);
    if ((t & 31) == 0) sred[t >> 5] = v;
    __syncthreads();
    if (t < 8) {
        int s = sred[t];
#pragma unroll
        for (int o = 4; o > 0; o >>= 1) s += __shfl_down_sync(0xffu, s, o);
        if (t == 0) g_bsum[b] = s;
    }
}

// K2b: single block scans NB block sums -> exclusive offsets
__global__ void k_scan2() {
    __shared__ int s[512];
    int t = threadIdx.x;
    int v = (t < NB) ? g_bsum[t] : 0;
    s[t] = v;
    __syncthreads();
    for (int off = 1; off < 512; off <<= 1) {
        int u = (t >= off) ? s[t - off] : 0;
        __syncthreads();
        s[t] += u;
        __syncthreads();
    }
    if (t < NB) g_boff[t] = s[t] - v;  // exclusive
    if (t == 0) g_rowst[NN] = NE;
}

// K2c: per-block coalesced scan -> rowst/rowcur/dinv
__global__ void k_scan3() {
    __shared__ int swarp[8];
    int b = blockIdx.x, t = threadIdx.x;
    int i = b * 256 + t;
    int lane = t & 31, w = t >> 5;
    int v = (i < NN) ? g_cnt[i] : 0;
    // warp inclusive scan
    int inc = v;
#pragma unroll
    for (int o = 1; o < 32; o <<= 1) {
        int u = __shfl_up_sync(0xffffffffu, inc, o);
        if (lane >= o) inc += u;
    }
    if (lane == 31) swarp[w] = inc;
    __syncthreads();
    if (t < 8) {
        int s = swarp[t];
#pragma unroll
        for (int o = 1; o < 8; o <<= 1) {
            int u = __shfl_up_sync(0xffu, s, o);
            if (t >= o) s += u;
        }
        swarp[t] = s;
    }
    __syncthreads();
    int excl = inc - v + (w ? swarp[w - 1] : 0) + g_boff[b];
    if (i < NN) {
        g_rowst[i]  = excl;
        g_rowcur[i] = excl;
        g_dinv[i]   = rsqrtf((float)(v + 1));
    }
}

// K3: CSR fill
__global__ void k_fill(const int* __restrict__ ei) {
    int e = blockIdx.x * blockDim.x + threadIdx.x;
    if (e >= NE) return;
    int src = ei[e];
    int dst = ei[NE + e];
    int pos = atomicAdd(&g_rowcur[dst], 1);
    g_csrc[pos] = src;
}

// K4: g1 = dinv * (x @ W1). 16 threads/node, float4 outputs.
__global__ void k_xw1(const float* __restrict__ x, const float* __restrict__ W1) {
    __shared__ float4 sW[FIN * 16];
    for (int i = threadIdx.x; i < FIN * 16; i += blockDim.x)
        sW[i] = ((const float4*)W1)[i];
    __syncthreads();
    int gid = blockIdx.x * blockDim.x + threadIdx.x;
    int node = gid >> 4;
    if (node >= NN) return;
    int c = gid & 15;
    const float* xr = x + node * FIN;
    float4 a = make_float4(0.f, 0.f, 0.f, 0.f);
#pragma unroll
    for (int k = 0; k < FIN; k++) {
        float xk = __ldg(xr + k);
        float4 w = sW[k * 16 + c];
        a.x += xk * w.x; a.y += xk * w.y; a.z += xk * w.z; a.w += xk * w.w;
    }
    float d = g_dinv[node];
    a.x *= d; a.y *= d; a.z *= d; a.w *= d;
    ((float4*)g_g1)[node * 16 + c] = a;
}

// K5/K7: CSR gather-aggregate: agg[i] = g[i] + sum_{j->i} g[j]. MLP-4 unroll.
__global__ void k_agg(int layer) {
    int gid = blockIdx.x * blockDim.x + threadIdx.x;
    int node = gid >> 4;
    if (node >= NN) return;
    int c = gid & 15;
    const float4* g   = layer ? (const float4*)g_g2 : (const float4*)g_g1;
    float4*       agg = layer ? (float4*)g_agg2     : (float4*)g_agg1;
    int beg = g_rowst[node];
    int end = g_rowst[node + 1];
    float4 acc = g[node * 16 + c];  // self-loop term
    int j = beg;
    for (; j + 4 <= end; j += 4) {
        int s0 = g_csrc[j];
        int s1 = g_csrc[j + 1];
        int s2 = g_csrc[j + 2];
        int s3 = g_csrc[j + 3];
        float4 v0 = g[s0 * 16 + c];
        float4 v1 = g[s1 * 16 + c];
        float4 v2 = g[s2 * 16 + c];
        float4 v3 = g[s3 * 16 + c];
        acc.x += (v0.x + v1.x) + (v2.x + v3.x);
        acc.y += (v0.y + v1.y) + (v2.y + v3.y);
        acc.z += (v0.z + v1.z) + (v2.z + v3.z);
        acc.w += (v0.w + v1.w) + (v2.w + v3.w);
    }
    for (; j < end; j++) {
        int s0 = g_csrc[j];
        float4 v0 = g[s0 * 16 + c];
        acc.x += v0.x; acc.y += v0.y; acc.z += v0.z; acc.w += v0.w;
    }
    agg[node * 16 + c] = acc;
}

// K6: h1 = tanh(dinv*agg1 + b1) (kept in smem); g2 = dinv * (h1 @ W2).
__global__ void k_l2(const float* __restrict__ W2, const float* __restrict__ b1) {
    __shared__ float sW[HID * HID];   // 16 KB
    __shared__ float sh[32 * HID];    // 8 KB
    int tid = threadIdx.x;
    for (int i = tid; i < HID * HID; i += 256) sW[i] = W2[i];
    int n0 = blockIdx.x * 32;
    for (int i = tid; i < 32 * HID; i += 256) {
        int node = n0 + (i >> 6);
        int f    = i & 63;
        sh[i] = tanhf(g_dinv[node] * g_agg1[node * HID + f] + b1[f]);
    }
    __syncthreads();
    for (int i = tid; i < 32 * HID; i += 256) {
        int ln = i >> 6;
        int f  = i & 63;
        const float* hr = sh + ln * HID;
        float s = 0.0f;
#pragma unroll 8
        for (int k = 0; k < HID; k++) s += hr[k] * sW[k * HID + f];
        int node = n0 + ln;
        g_g2[node * HID + f] = g_dinv[node] * s;
    }
}

// K8: pooling. batch sorted -> block per (graph, split); lane per feature.
__global__ void k_pool(const float* __restrict__ x,
                       const float* __restrict__ b1,
                       const float* __restrict__ b2,
                       const int* __restrict__ batch) {
    int g = blockIdx.x / SPLIT;
    int s = blockIdx.x % SPLIT;
    int f = threadIdx.x;

    int a = 0, b = NN;
    while (a < b) { int m = (a + b) >> 1; if (batch[m] < g) a = m + 1; else b = m; }
    int lo = a;
    a = lo; b = NN;
    while (a < b) { int m = (a + b) >> 1; if (batch[m] < g + 1) a = m + 1; else b = m; }
    int hi = a;

    int cnt = hi - lo;
    int per = (cnt + SPLIT - 1) / SPLIT;
    int st  = lo + s * per;
    int en  = min(st + per, hi);

    if (f < FCD) {
        float acc = 0.0f;
        for (int node = st; node < en; node++) {
            float v;
            if (f < FIN) {
                v = x[node * FIN + f];
            } else if (f < FIN + HID) {
                int k = f - FIN;
                v = tanhf(g_dinv[node] * g_agg1[node * HID + k] + b1[k]);
            } else {
                int k = f - FIN - HID;
                v = tanhf(g_dinv[node] * g_agg2[node * HID + k] + b2[k]);
            }
            acc += v;
        }
        if (st < en) atomicAdd(&g_pooled[g * FCD + f], acc);
    }
}

// K9: out[g,o] = sum_k pooled[g,k] * fc_W[o,k] + fc_b[o]
__global__ void k_fc(const float* __restrict__ fcW,
                     const float* __restrict__ fcb,
                     float* __restrict__ out) {
    __shared__ float sp[FCD];
    int g = blockIdx.x;
    for (int i = threadIdx.x; i < FCD; i += blockDim.x) sp[i] = g_pooled[g * FCD + i];
    __syncthreads();
    int o = threadIdx.x;
    if (o < FCD) {
        const float* wr = fcW + o * FCD;
        float s = fcb[o];
        for (int k = 0; k < FCD; k++) s += sp[k] * wr[k];
        out[g * FCD + o] = s;
    }
}

// ---------------------------------------------------------------------------
extern "C" void kernel_launch(void* const* d_in, const int* in_sizes, int n_in,
                              void* d_out, int out_size) {
    const float* x    = (const float*)d_in[0];
    const float* W1   = (const float*)d_in[1];
    const float* b1   = (const float*)d_in[2];
    const float* W2   = (const float*)d_in[3];
    const float* b2   = (const float*)d_in[4];
    const float* fcW  = (const float*)d_in[5];
    const float* fcb  = (const float*)d_in[6];
    const int*   ei   = (const int*)d_in[7];     // int32
    const int*   batch= (const int*)d_in[8];     // int32
    float* out = (float*)d_out;
    (void)in_sizes; (void)n_in; (void)out_size;

    k_init <<<(NN + 255) / 256, 256>>>();
    k_deg  <<<(NE + 255) / 256, 256>>>(ei);
    k_scan1<<<NB, 256>>>();
    k_scan2<<<1, 512>>>();
    k_scan3<<<NB, 256>>>();
    k_fill <<<(NE + 255) / 256, 256>>>(ei);
    k_xw1  <<<(NN * 16 + 255) / 256, 256>>>(x, W1);
    k_agg  <<<(NN * 16 + 255) / 256, 256>>>(0);
    k_l2   <<<(NN + 31) / 32, 256>>>(W2, b1);
    k_agg  <<<(NN * 16 + 255) / 256, 256>>>(1);
    k_pool <<<NG * SPLIT, 160>>>(x, b1, b2, batch);
    k_fc   <<<NG, 160>>>(fcW, fcb, out);
}

// round 7
// speedup vs baseline: 2.2733x; 1.3132x over previous
#include <cuda_runtime.h>
#include <math.h>

#define NN 100000
#define NE 1600000
#define NG 256
#define FIN 12
#define HID 64
#define FCD 140
#define SPLIT 8
#define NB 391          // 391*256 = 100096 >= NN

// Scratch (static __device__ — no allocation allowed)
__device__ __align__(16) float g_y[NN * 16];     // dinv*x padded to 16
__device__ __align__(16) float g_aggx[NN * 16];  // aggregated 12-dim (padded)
__device__ __align__(16) float g_z[NN * HID];    // dinv*h1
__device__ __align__(16) float g_aggz[NN * HID];
__device__ __align__(16) float g_h2[NN * HID];
__device__ float g_dinv[NN];
__device__ float g_sq[NN];           // sqrt(deg) = 1/dinv
__device__ int   g_cnt[NN];
__device__ int   g_rowst[NN + 1];
__device__ int   g_rowcur[NN];
__device__ int   g_csrc[NE];
__device__ int   g_bsum[NB];
__device__ int   g_boff[NB];
__device__ float g_pooled[NG * FCD];

// ---------------------------------------------------------------------------
__global__ void k_init() {
    int i = blockIdx.x * blockDim.x + threadIdx.x;
    if (i < NN) g_cnt[i] = 0;
    if (i < NG * FCD) g_pooled[i] = 0.0f;
}

__global__ void k_deg(const int* __restrict__ ei) {
    int e = blockIdx.x * blockDim.x + threadIdx.x;
    if (e < NE) atomicAdd(&g_cnt[ei[NE + e]], 1);
}

// coalesced per-block sums of cnt
__global__ void k_scan1() {
    __shared__ int sred[8];
    int b = blockIdx.x, t = threadIdx.x;
    int i = b * 256 + t;
    int v = (i < NN) ? g_cnt[i] : 0;
#pragma unroll
    for (int o = 16; o > 0; o >>= 1) v += __shfl_down_sync(0xffffffffu, v, o);
    if ((t & 31) == 0) sred[t >> 5] = v;
    __syncthreads();
    if (t < 8) {
        int s = sred[t];
#pragma unroll
        for (int o = 4; o > 0; o >>= 1) s += __shfl_down_sync(0xffu, s, o);
        if (t == 0) g_bsum[b] = s;
    }
}

__global__ void k_scan2() {
    __shared__ int s[512];
    int t = threadIdx.x;
    int v = (t < NB) ? g_bsum[t] : 0;
    s[t] = v;
    __syncthreads();
    for (int off = 1; off < 512; off <<= 1) {
        int u = (t >= off) ? s[t - off] : 0;
        __syncthreads();
        s[t] += u;
        __syncthreads();
    }
    if (t < NB) g_boff[t] = s[t] - v;
    if (t == 0) g_rowst[NN] = NE;
}

__global__ void k_scan3() {
    __shared__ int swarp[8];
    int b = blockIdx.x, t = threadIdx.x;
    int i = b * 256 + t;
    int lane = t & 31, w = t >> 5;
    int v = (i < NN) ? g_cnt[i] : 0;
    int inc = v;
#pragma unroll
    for (int o = 1; o < 32; o <<= 1) {
        int u = __shfl_up_sync(0xffffffffu, inc, o);
        if (lane >= o) inc += u;
    }
    if (lane == 31) swarp[w] = inc;
    __syncthreads();
    if (t < 8) {
        int s = swarp[t];
#pragma unroll
        for (int o = 1; o < 8; o <<= 1) {
            int u = __shfl_up_sync(0xffu, s, o);
            if (t >= o) s += u;
        }
        swarp[t] = s;
    }
    __syncthreads();
    int excl = inc - v + (w ? swarp[w - 1] : 0) + g_boff[b];
    if (i < NN) {
        g_rowst[i]  = excl;
        g_rowcur[i] = excl;
        float deg = (float)(v + 1);
        g_dinv[i] = rsqrtf(deg);
        g_sq[i]   = sqrtf(deg);
    }
}

__global__ void k_fill(const int* __restrict__ ei) {
    int e = blockIdx.x * blockDim.x + threadIdx.x;
    if (e >= NE) return;
    int src = ei[e];
    int dst = ei[NE + e];
    int pos = atomicAdd(&g_rowcur[dst], 1);
    g_csrc[pos] = src;
}

// y16[node][0..11] = dinv*x, [12..15]=0. 4 lanes/node, float4.
__global__ void k_pre(const float* __restrict__ x) {
    int gid = blockIdx.x * blockDim.x + threadIdx.x;
    int node = gid >> 2;
    if (node >= NN) return;
    int c = gid & 3;
    float4 v = make_float4(0.f, 0.f, 0.f, 0.f);
    if (c < 3) {
        float4 xv = ((const float4*)x)[node * 3 + c];
        float d = g_dinv[node];
        v = make_float4(xv.x * d, xv.y * d, xv.z * d, xv.w * d);
    }
    ((float4*)g_y)[node * 4 + c] = v;
}

// 12-dim CSR gather: aggx[i] = y[i] + sum_{j->i} y[j]. 4 lanes/node.
__global__ void k_agg12() {
    int gid = blockIdx.x * blockDim.x + threadIdx.x;
    int node = gid >> 2;
    if (node >= NN) return;
    int c = gid & 3;
    int beg = g_rowst[node];
    int end = g_rowst[node + 1];
    float4 acc = ((const float4*)g_y)[node * 4 + c];
    int j = beg;
    for (; j + 4 <= end; j += 4) {
        int s0 = g_csrc[j];
        int s1 = g_csrc[j + 1];
        int s2 = g_csrc[j + 2];
        int s3 = g_csrc[j + 3];
        float4 v0 = ((const float4*)g_y)[s0 * 4 + c];
        float4 v1 = ((const float4*)g_y)[s1 * 4 + c];
        float4 v2 = ((const float4*)g_y)[s2 * 4 + c];
        float4 v3 = ((const float4*)g_y)[s3 * 4 + c];
        acc.x += (v0.x + v1.x) + (v2.x + v3.x);
        acc.y += (v0.y + v1.y) + (v2.y + v3.y);
        acc.z += (v0.z + v1.z) + (v2.z + v3.z);
        acc.w += (v0.w + v1.w) + (v2.w + v3.w);
    }
    for (; j < end; j++) {
        int s0 = g_csrc[j];
        float4 v0 = ((const float4*)g_y)[s0 * 4 + c];
        acc.x += v0.x; acc.y += v0.y; acc.z += v0.z; acc.w += v0.w;
    }
    ((float4*)g_aggx)[node * 4 + c] = acc;
}

// h1 = tanh(dinv*(aggx@W1)+b1); z = dinv*h1. 16 fgroups/node, 16 nodes/block.
__global__ void k_l1(const float* __restrict__ W1, const float* __restrict__ b1) {
    __shared__ float4 sW[FIN * 16];   // W1 rows as float4 groups
    __shared__ float  sb[HID];
    int t = threadIdx.x;
    if (t < FIN * 16) sW[t] = ((const float4*)W1)[t];
    if (t < HID) sb[t] = b1[t];
    __syncthreads();
    int node = blockIdx.x * 16 + (t >> 4);
    if (node >= NN) return;
    int fg = t & 15;
    float4 a0 = ((const float4*)g_aggx)[node * 4 + 0];
    float4 a1 = ((const float4*)g_aggx)[node * 4 + 1];
    float4 a2 = ((const float4*)g_aggx)[node * 4 + 2];
    float av[12] = {a0.x, a0.y, a0.z, a0.w, a1.x, a1.y, a1.z, a1.w,
                    a2.x, a2.y, a2.z, a2.w};
    float4 acc = make_float4(0.f, 0.f, 0.f, 0.f);
#pragma unroll
    for (int k = 0; k < FIN; k++) {
        float4 w = sW[k * 16 + fg];
        float ak = av[k];
        acc.x += ak * w.x; acc.y += ak * w.y; acc.z += ak * w.z; acc.w += ak * w.w;
    }
    float d = g_dinv[node];
    float4 z;
    z.x = d * tanhf(d * acc.x + sb[fg * 4 + 0]);
    z.y = d * tanhf(d * acc.y + sb[fg * 4 + 1]);
    z.z = d * tanhf(d * acc.z + sb[fg * 4 + 2]);
    z.w = d * tanhf(d * acc.w + sb[fg * 4 + 3]);
    ((float4*)g_z)[node * 16 + fg] = z;
}

// 64-dim CSR gather: aggz[i] = z[i] + sum_{j->i} z[j]. 16 lanes/node.
__global__ void k_aggz() {
    int gid = blockIdx.x * blockDim.x + threadIdx.x;
    int node = gid >> 4;
    if (node >= NN) return;
    int c = gid & 15;
    int beg = g_rowst[node];
    int end = g_rowst[node + 1];
    float4 acc = ((const float4*)g_z)[node * 16 + c];
    int j = beg;
    for (; j + 4 <= end; j += 4) {
        int s0 = g_csrc[j];
        int s1 = g_csrc[j + 1];
        int s2 = g_csrc[j + 2];
        int s3 = g_csrc[j + 3];
        float4 v0 = ((const float4*)g_z)[s0 * 16 + c];
        float4 v1 = ((const float4*)g_z)[s1 * 16 + c];
        float4 v2 = ((const float4*)g_z)[s2 * 16 + c];
        float4 v3 = ((const float4*)g_z)[s3 * 16 + c];
        acc.x += (v0.x + v1.x) + (v2.x + v3.x);
        acc.y += (v0.y + v1.y) + (v2.y + v3.y);
        acc.z += (v0.z + v1.z) + (v2.z + v3.z);
        acc.w += (v0.w + v1.w) + (v2.w + v3.w);
    }
    for (; j < end; j++) {
        int s0 = g_csrc[j];
        float4 v0 = ((const float4*)g_z)[s0 * 16 + c];
        acc.x += v0.x; acc.y += v0.y; acc.z += v0.z; acc.w += v0.w;
    }
    ((float4*)g_aggz)[node * 16 + c] = acc;
}

// h2 = tanh(dinv*(aggz@W2)+b2). 32 nodes/block, 128 threads, 4f x 4n tiles.
__global__ void k_l2(const float* __restrict__ W2, const float* __restrict__ b2) {
    __shared__ float4 sW[HID * 16];      // 16 KB: W2[k][f] as float4 groups
    __shared__ float  sA[HID * 36];      // 9 KB: aggz transposed [k][node], pad 36
    __shared__ float  sb[HID];
    int t = threadIdx.x;
    int n0 = blockIdx.x * 32;
    // load W2 (1024 float4) and b2
    for (int i = t; i < HID * 16; i += 128) sW[i] = ((const float4*)W2)[i];
    if (t < HID) sb[t] = b2[t];
    // load aggz tile transposed: thread t -> node n=t>>2, quarter q=t&3 (16 k's)
    {
        int n = t >> 2, q = t & 3;
#pragma unroll
        for (int i = 0; i < 4; i++) {
            float4 v = ((const float4*)g_aggz)[(n0 + n) * 16 + q * 4 + i];
            int k = q * 16 + i * 4;
            sA[(k + 0) * 36 + n] = v.x;
            sA[(k + 1) * 36 + n] = v.y;
            sA[(k + 2) * 36 + n] = v.z;
            sA[(k + 3) * 36 + n] = v.w;
        }
    }
    __syncthreads();
    int fg = t & 15;        // feature group (4 features)
    int ng = t >> 4;        // node group (4 nodes), 0..7
    float4 acc[4];
#pragma unroll
    for (int i = 0; i < 4; i++) acc[i] = make_float4(0.f, 0.f, 0.f, 0.f);
#pragma unroll 8
    for (int k = 0; k < HID; k++) {
        float4 w = sW[k * 16 + fg];
        const float4 a = *(const float4*)&sA[k * 36 + ng * 4];
        acc[0].x += a.x * w.x; acc[0].y += a.x * w.y; acc[0].z += a.x * w.z; acc[0].w += a.x * w.w;
        acc[1].x += a.y * w.x; acc[1].y += a.y * w.y; acc[1].z += a.y * w.z; acc[1].w += a.y * w.w;
        acc[2].x += a.z * w.x; acc[2].y += a.z * w.y; acc[2].z += a.z * w.z; acc[2].w += a.z * w.w;
        acc[3].x += a.w * w.x; acc[3].y += a.w * w.y; acc[3].z += a.w * w.z; acc[3].w += a.w * w.w;
    }
    float4 bb = *(const float4*)&sb[fg * 4];
#pragma unroll
    for (int i = 0; i < 4; i++) {
        int node = n0 + ng * 4 + i;
        float d = g_dinv[node];
        float4 h;
        h.x = tanhf(d * acc[i].x + bb.x);
        h.y = tanhf(d * acc[i].y + bb.y);
        h.z = tanhf(d * acc[i].z + bb.z);
        h.w = tanhf(d * acc[i].w + bb.w);
        ((float4*)g_h2)[node * 16 + fg] = h;
    }
}

// pooling: batch sorted -> block per (graph, split); lane per feature.
__global__ void k_pool(const float* __restrict__ x,
                       const int* __restrict__ batch) {
    int g = blockIdx.x / SPLIT;
    int s = blockIdx.x % SPLIT;
    int f = threadIdx.x;

    int a = 0, b = NN;
    while (a < b) { int m = (a + b) >> 1; if (batch[m] < g) a = m + 1; else b = m; }
    int lo = a;
    a = lo; b = NN;
    while (a < b) { int m = (a + b) >> 1; if (batch[m] < g + 1) a = m + 1; else b = m; }
    int hi = a;

    int cnt = hi - lo;
    int per = (cnt + SPLIT - 1) / SPLIT;
    int st  = lo + s * per;
    int en  = min(st + per, hi);

    if (f < FCD) {
        float acc = 0.0f;
        for (int node = st; node < en; node++) {
            float v;
            if (f < FIN) {
                v = x[node * FIN + f];
            } else if (f < FIN + HID) {
                v = g_z[node * HID + (f - FIN)] * g_sq[node];  // h1 = z*sqrt(deg)
            } else {
                v = g_h2[node * HID + (f - FIN - HID)];
            }
            acc += v;
        }
        if (st < en) atomicAdd(&g_pooled[g * FCD + f], acc);
    }
}

__global__ void k_fc(const float* __restrict__ fcW,
                     const float* __restrict__ fcb,
                     float* __restrict__ out) {
    __shared__ float sp[FCD];
    int g = blockIdx.x;
    for (int i = threadIdx.x; i < FCD; i += blockDim.x) sp[i] = g_pooled[g * FCD + i];
    __syncthreads();
    int o = threadIdx.x;
    if (o < FCD) {
        const float* wr = fcW + o * FCD;
        float s = fcb[o];
        for (int k = 0; k < FCD; k++) s += sp[k] * wr[k];
        out[g * FCD + o] = s;
    }
}

// ---------------------------------------------------------------------------
extern "C" void kernel_launch(void* const* d_in, const int* in_sizes, int n_in,
                              void* d_out, int out_size) {
    const float* x    = (const float*)d_in[0];
    const float* W1   = (const float*)d_in[1];
    const float* b1   = (const float*)d_in[2];
    const float* W2   = (const float*)d_in[3];
    const float* b2   = (const float*)d_in[4];
    const float* fcW  = (const float*)d_in[5];
    const float* fcb  = (const float*)d_in[6];
    const int*   ei   = (const int*)d_in[7];
    const int*   batch= (const int*)d_in[8];
    float* out = (float*)d_out;
    (void)in_sizes; (void)n_in; (void)out_size;

    k_init <<<(NN + 255) / 256, 256>>>();
    k_deg  <<<(NE + 255) / 256, 256>>>(ei);
    k_scan1<<<NB, 256>>>();
    k_scan2<<<1, 512>>>();
    k_scan3<<<NB, 256>>>();
    k_fill <<<(NE + 255) / 256, 256>>>(ei);
    k_pre  <<<(NN * 4 + 255) / 256, 256>>>(x);
    k_agg12<<<(NN * 4 + 255) / 256, 256>>>();
    k_l1   <<<(NN + 15) / 16, 256>>>(W1, b1);
    k_aggz <<<(NN * 16 + 255) / 256, 256>>>();
    k_l2   <<<NN / 32, 128>>>(W2, b2);
    k_pool <<<NG * SPLIT, 160>>>(x, batch);
    k_fc   <<<NG, 160>>>(fcW, fcb, out);
}

// round 8
// speedup vs baseline: 2.4364x; 1.0718x over previous
#include <cuda_runtime.h>
#include <cuda_fp16.h>
#include <math.h>

#define NN 100000
#define NE 1600000
#define NG 256
#define FIN 12
#define HID 64
#define FCD 140
#define SPLIT 8
#define NB 391          // 391*256 = 100096 >= NN

// Scratch (static __device__ — no allocation allowed)
__device__ __align__(16) float  g_y[NN * 16];     // dinv*x padded to 16
__device__ __align__(16) float  g_aggx[NN * 16];  // aggregated 12-dim (padded)
__device__ __align__(16) __half g_zh[NN * HID];   // dinv*h1, fp16
__device__ __align__(16) float  g_aggz[NN * HID]; // fp32 accumulated
__device__ __align__(16) __half g_h2h[NN * HID];  // h2, fp16
__device__ float g_dinv[NN];
__device__ float g_sq[NN];            // sqrt(deg)
__device__ int   g_cnt[NN];
__device__ int   g_rowst[NN + 1];
__device__ int   g_rowcur[NN];
__device__ int   g_csrc[NE];
__device__ int   g_bsum[NB];
__device__ float g_pooled[NG * FCD];

// ---------------------------------------------------------------------------
__global__ void k_init() {
    int i = blockIdx.x * blockDim.x + threadIdx.x;
    if (i < NN) g_cnt[i] = 0;
    if (i < NG * FCD) g_pooled[i] = 0.0f;
}

__global__ void k_deg(const int* __restrict__ ei) {
    int e = blockIdx.x * blockDim.x + threadIdx.x;
    if (e < NE) atomicAdd(&g_cnt[ei[NE + e]], 1);
}

// per-block sums of cnt
__global__ void k_scan1() {
    __shared__ int sred[8];
    int b = blockIdx.x, t = threadIdx.x;
    int i = b * 256 + t;
    int v = (i < NN) ? g_cnt[i] : 0;
#pragma unroll
    for (int o = 16; o > 0; o >>= 1) v += __shfl_down_sync(0xffffffffu, v, o);
    if ((t & 31) == 0) sred[t >> 5] = v;
    __syncthreads();
    if (t < 8) {
        int s = sred[t];
#pragma unroll
        for (int o = 4; o > 0; o >>= 1) s += __shfl_down_sync(0xffu, s, o);
        if (t == 0) g_bsum[b] = s;
    }
}

// per-block scan with inline block-offset reduction (replaces scan2+scan3)
__global__ void k_scan3() {
    __shared__ int sred[8];
    __shared__ int swarp[8];
    __shared__ int sboff;
    int b = blockIdx.x, t = threadIdx.x;
    int lane = t & 31, w = t >> 5;

    // boff = sum of bsum[0..b)
    int s = 0;
    for (int i = t; i < b; i += 256) s += g_bsum[i];
#pragma unroll
    for (int o = 16; o > 0; o >>= 1) s += __shfl_down_sync(0xffffffffu, s, o);
    if (lane == 0) sred[w] = s;
    __syncthreads();
    if (t < 8) {
        int r = sred[t];
#pragma unroll
        for (int o = 4; o > 0; o >>= 1) r += __shfl_down_sync(0xffu, r, o);
        if (t == 0) sboff = r;
    }

    // per-element inclusive scan within the block
    int i = b * 256 + t;
    int v = (i < NN) ? g_cnt[i] : 0;
    int inc = v;
#pragma unroll
    for (int o = 1; o < 32; o <<= 1) {
        int u = __shfl_up_sync(0xffffffffu, inc, o);
        if (lane >= o) inc += u;
    }
    if (lane == 31) swarp[w] = inc;
    __syncthreads();   // publishes swarp AND sboff
    if (t < 8) {
        int s2 = swarp[t];
#pragma unroll
        for (int o = 1; o < 8; o <<= 1) {
            int u = __shfl_up_sync(0xffu, s2, o);
            if (t >= o) s2 += u;
        }
        swarp[t] = s2;
    }
    __syncthreads();
    int excl = inc - v + (w ? swarp[w - 1] : 0) + sboff;
    if (i < NN) {
        g_rowst[i]  = excl;
        g_rowcur[i] = excl;
        float deg = (float)(v + 1);
        g_dinv[i] = rsqrtf(deg);
        g_sq[i]   = sqrtf(deg);
    }
    if (b == 0 && t == 0) g_rowst[NN] = NE;
}

// CSR fill, 4 edges/thread (MLP-4 over the atomic->store chain)
__global__ void k_fill(const int* __restrict__ ei) {
    int base = (blockIdx.x * blockDim.x + threadIdx.x) * 4;
    if (base >= NE) return;
    int s0[4], pos[4];
    int n = min(4, NE - base);
#pragma unroll
    for (int i = 0; i < 4; i++) {
        if (i < n) {
            s0[i] = ei[base + i];
            int d = ei[NE + base + i];
            pos[i] = atomicAdd(&g_rowcur[d], 1);
        }
    }
#pragma unroll
    for (int i = 0; i < 4; i++)
        if (i < n) g_csrc[pos[i]] = s0[i];
}

// y16[node][0..11] = dinv*x, [12..15]=0. 4 lanes/node.
__global__ void k_pre(const float* __restrict__ x) {
    int gid = blockIdx.x * blockDim.x + threadIdx.x;
    int node = gid >> 2;
    if (node >= NN) return;
    int c = gid & 3;
    float4 v = make_float4(0.f, 0.f, 0.f, 0.f);
    if (c < 3) {
        float4 xv = ((const float4*)x)[node * 3 + c];
        float d = g_dinv[node];
        v = make_float4(xv.x * d, xv.y * d, xv.z * d, xv.w * d);
    }
    ((float4*)g_y)[node * 4 + c] = v;
}

// 12-dim CSR gather. 4 lanes/node.
__global__ void k_agg12() {
    int gid = blockIdx.x * blockDim.x + threadIdx.x;
    int node = gid >> 2;
    if (node >= NN) return;
    int c = gid & 3;
    int beg = g_rowst[node];
    int end = g_rowst[node + 1];
    float4 acc = ((const float4*)g_y)[node * 4 + c];
    int j = beg;
    for (; j + 4 <= end; j += 4) {
        int s0 = g_csrc[j];
        int s1 = g_csrc[j + 1];
        int s2 = g_csrc[j + 2];
        int s3 = g_csrc[j + 3];
        float4 v0 = ((const float4*)g_y)[s0 * 4 + c];
        float4 v1 = ((const float4*)g_y)[s1 * 4 + c];
        float4 v2 = ((const float4*)g_y)[s2 * 4 + c];
        float4 v3 = ((const float4*)g_y)[s3 * 4 + c];
        acc.x += (v0.x + v1.x) + (v2.x + v3.x);
        acc.y += (v0.y + v1.y) + (v2.y + v3.y);
        acc.z += (v0.z + v1.z) + (v2.z + v3.z);
        acc.w += (v0.w + v1.w) + (v2.w + v3.w);
    }
    for (; j < end; j++) {
        int s0 = g_csrc[j];
        float4 v0 = ((const float4*)g_y)[s0 * 4 + c];
        acc.x += v0.x; acc.y += v0.y; acc.z += v0.z; acc.w += v0.w;
    }
    ((float4*)g_aggx)[node * 4 + c] = acc;
}

// h1 = tanh(dinv*(aggx@W1)+b1); z = dinv*h1 stored fp16. 16 fg/node.
__global__ void k_l1(const float* __restrict__ W1, const float* __restrict__ b1) {
    __shared__ float4 sW[FIN * 16];
    __shared__ float  sb[HID];
    int t = threadIdx.x;
    if (t < FIN * 16) sW[t] = ((const float4*)W1)[t];
    if (t < HID) sb[t] = b1[t];
    __syncthreads();
    int node = blockIdx.x * 16 + (t >> 4);
    if (node >= NN) return;
    int fg = t & 15;
    float4 a0 = ((const float4*)g_aggx)[node * 4 + 0];
    float4 a1 = ((const float4*)g_aggx)[node * 4 + 1];
    float4 a2 = ((const float4*)g_aggx)[node * 4 + 2];
    float av[12] = {a0.x, a0.y, a0.z, a0.w, a1.x, a1.y, a1.z, a1.w,
                    a2.x, a2.y, a2.z, a2.w};
    float4 acc = make_float4(0.f, 0.f, 0.f, 0.f);
#pragma unroll
    for (int k = 0; k < FIN; k++) {
        float4 w = sW[k * 16 + fg];
        float ak = av[k];
        acc.x += ak * w.x; acc.y += ak * w.y; acc.z += ak * w.z; acc.w += ak * w.w;
    }
    float d = g_dinv[node];
    float zx = d * tanhf(d * acc.x + sb[fg * 4 + 0]);
    float zy = d * tanhf(d * acc.y + sb[fg * 4 + 1]);
    float zz = d * tanhf(d * acc.z + sb[fg * 4 + 2]);
    float zw = d * tanhf(d * acc.w + sb[fg * 4 + 3]);
    __half2 p0 = __floats2half2_rn(zx, zy);
    __half2 p1 = __floats2half2_rn(zz, zw);
    uint2 pk;
    pk.x = *(unsigned*)&p0;
    pk.y = *(unsigned*)&p1;
    ((uint2*)g_zh)[node * 16 + fg] = pk;
}

// 64-dim fp16 CSR gather, fp32 accumulate. 8 lanes/node, 16B (8 halves) each.
__global__ void k_aggz() {
    int gid = blockIdx.x * blockDim.x + threadIdx.x;
    int node = gid >> 3;
    if (node >= NN) return;
    int c = gid & 7;
    int beg = g_rowst[node];
    int end = g_rowst[node + 1];
    const uint4* z = (const uint4*)g_zh;

    float2 a[4];
    {
        uint4 v = z[node * 8 + c];
        const __half2* h = (const __half2*)&v;
#pragma unroll
        for (int i = 0; i < 4; i++) a[i] = __half22float2(h[i]);
    }
    int j = beg;
    for (; j + 4 <= end; j += 4) {
        int s0 = g_csrc[j];
        int s1 = g_csrc[j + 1];
        int s2 = g_csrc[j + 2];
        int s3 = g_csrc[j + 3];
        uint4 v0 = z[s0 * 8 + c];
        uint4 v1 = z[s1 * 8 + c];
        uint4 v2 = z[s2 * 8 + c];
        uint4 v3 = z[s3 * 8 + c];
#pragma unroll
        for (int i = 0; i < 4; i++) {
            float2 f0 = __half22float2(((const __half2*)&v0)[i]);
            float2 f1 = __half22float2(((const __half2*)&v1)[i]);
            float2 f2 = __half22float2(((const __half2*)&v2)[i]);
            float2 f3 = __half22float2(((const __half2*)&v3)[i]);
            a[i].x += (f0.x + f1.x) + (f2.x + f3.x);
            a[i].y += (f0.y + f1.y) + (f2.y + f3.y);
        }
    }
    for (; j < end; j++) {
        uint4 v0 = z[g_csrc[j] * 8 + c];
#pragma unroll
        for (int i = 0; i < 4; i++) {
            float2 f0 = __half22float2(((const __half2*)&v0)[i]);
            a[i].x += f0.x; a[i].y += f0.y;
        }
    }
    float4 o0 = make_float4(a[0].x, a[0].y, a[1].x, a[1].y);
    float4 o1 = make_float4(a[2].x, a[2].y, a[3].x, a[3].y);
    ((float4*)g_aggz)[node * 16 + c * 2 + 0] = o0;
    ((float4*)g_aggz)[node * 16 + c * 2 + 1] = o1;
}

// h2 = tanh(dinv*(aggz@W2)+b2) stored fp16. 32 nodes/block, 128 thr, 4x4 tiles.
__global__ void k_l2(const float* __restrict__ W2, const float* __restrict__ b2) {
    __shared__ float4 sW[HID * 16];      // 16 KB
    __shared__ float  sA[HID * 36];      // 9 KB transposed, pad 36
    __shared__ float  sb[HID];
    int t = threadIdx.x;
    int n0 = blockIdx.x * 32;
    for (int i = t; i < HID * 16; i += 128) sW[i] = ((const float4*)W2)[i];
    if (t < HID) sb[t] = b2[t];
    {
        int n = t >> 2, q = t & 3;
#pragma unroll
        for (int i = 0; i < 4; i++) {
            float4 v = ((const float4*)g_aggz)[(n0 + n) * 16 + q * 4 + i];
            int k = q * 16 + i * 4;
            sA[(k + 0) * 36 + n] = v.x;
            sA[(k + 1) * 36 + n] = v.y;
            sA[(k + 2) * 36 + n] = v.z;
            sA[(k + 3) * 36 + n] = v.w;
        }
    }
    __syncthreads();
    int fg = t & 15;
    int ng = t >> 4;
    float4 acc[4];
#pragma unroll
    for (int i = 0; i < 4; i++) acc[i] = make_float4(0.f, 0.f, 0.f, 0.f);
#pragma unroll 8
    for (int k = 0; k < HID; k++) {
        float4 w = sW[k * 16 + fg];
        const float4 a = *(const float4*)&sA[k * 36 + ng * 4];
        acc[0].x += a.x * w.x; acc[0].y += a.x * w.y; acc[0].z += a.x * w.z; acc[0].w += a.x * w.w;
        acc[1].x += a.y * w.x; acc[1].y += a.y * w.y; acc[1].z += a.y * w.z; acc[1].w += a.y * w.w;
        acc[2].x += a.z * w.x; acc[2].y += a.z * w.y; acc[2].z += a.z * w.z; acc[2].w += a.z * w.w;
        acc[3].x += a.w * w.x; acc[3].y += a.w * w.y; acc[3].z += a.w * w.z; acc[3].w += a.w * w.w;
    }
    float4 bb = *(const float4*)&sb[fg * 4];
#pragma unroll
    for (int i = 0; i < 4; i++) {
        int node = n0 + ng * 4 + i;
        float d = g_dinv[node];
        __half2 p0 = __floats2half2_rn(tanhf(d * acc[i].x + bb.x),
                                       tanhf(d * acc[i].y + bb.y));
        __half2 p1 = __floats2half2_rn(tanhf(d * acc[i].z + bb.z),
                                       tanhf(d * acc[i].w + bb.w));
        uint2 pk;
        pk.x = *(unsigned*)&p0;
        pk.y = *(unsigned*)&p1;
        ((uint2*)g_h2h)[node * 16 + fg] = pk;
    }
}

// pooling: batch sorted -> block per (graph, split); lane per feature.
__global__ void k_pool(const float* __restrict__ x,
                       const int* __restrict__ batch) {
    int g = blockIdx.x / SPLIT;
    int s = blockIdx.x % SPLIT;
    int f = threadIdx.x;

    int a = 0, b = NN;
    while (a < b) { int m = (a + b) >> 1; if (batch[m] < g) a = m + 1; else b = m; }
    int lo = a;
    a = lo; b = NN;
    while (a < b) { int m = (a + b) >> 1; if (batch[m] < g + 1) a = m + 1; else b = m; }
    int hi = a;

    int cnt = hi - lo;
    int per = (cnt + SPLIT - 1) / SPLIT;
    int st  = lo + s * per;
    int en  = min(st + per, hi);

    if (f < FCD) {
        float acc = 0.0f;
        for (int node = st; node < en; node++) {
            float v;
            if (f < FIN) {
                v = x[node * FIN + f];
            } else if (f < FIN + HID) {
                v = __half2float(g_zh[node * HID + (f - FIN)]) * g_sq[node];
            } else {
                v = __half2float(g_h2h[node * HID + (f - FIN - HID)]);
            }
            acc += v;
        }
        if (st < en) atomicAdd(&g_pooled[g * FCD + f], acc);
    }
}

__global__ void k_fc(const float* __restrict__ fcW,
                     const float* __restrict__ fcb,
                     float* __restrict__ out) {
    __shared__ float sp[FCD];
    int g = blockIdx.x;
    for (int i = threadIdx.x; i < FCD; i += blockDim.x) sp[i] = g_pooled[g * FCD + i];
    __syncthreads();
    int o = threadIdx.x;
    if (o < FCD) {
        const float* wr = fcW + o * FCD;
        float s = fcb[o];
        for (int k = 0; k < FCD; k++) s += sp[k] * wr[k];
        out[g * FCD + o] = s;
    }
}

// ---------------------------------------------------------------------------
extern "C" void kernel_launch(void* const* d_in, const int* in_sizes, int n_in,
                              void* d_out, int out_size) {
    const float* x    = (const float*)d_in[0];
    const float* W1   = (const float*)d_in[1];
    const float* b1   = (const float*)d_in[2];
    const float* W2   = (const float*)d_in[3];
    const float* b2   = (const float*)d_in[4];
    const float* fcW  = (const float*)d_in[5];
    const float* fcb  = (const float*)d_in[6];
    const int*   ei   = (const int*)d_in[7];
    const int*   batch= (const int*)d_in[8];
    float* out = (float*)d_out;
    (void)in_sizes; (void)n_in; (void)out_size;

    k_init <<<(NN + 255) / 256, 256>>>();
    k_deg  <<<(NE + 255) / 256, 256>>>(ei);
    k_scan1<<<NB, 256>>>();
    k_scan3<<<NB, 256>>>();
    k_fill <<<(NE / 4 + 255) / 256, 256>>>(ei);
    k_pre  <<<(NN * 4 + 255) / 256, 256>>>(x);
    k_agg12<<<(NN * 4 + 255) / 256, 256>>>();
    k_l1   <<<(NN + 15) / 16, 256>>>(W1, b1);
    k_aggz <<<(NN * 8 + 255) / 256, 256>>>();
    k_l2   <<<NN / 32, 128>>>(W2, b2);
    k_pool <<<NG * SPLIT, 160>>>(x, batch);
    k_fc   <<<NG, 160>>>(fcW, fcb, out);
}

// round 9
// speedup vs baseline: 2.6700x; 1.0959x over previous
#include <cuda_runtime.h>
#include <cuda_fp16.h>
#include <math.h>

#define NN 100000
#define NE 1600000
#define NG 256
#define FIN 12
#define HID 64
#define FCD 140
#define SPLIT 8
#define NB 391          // 391*256 = 100096 >= NN

// Scratch (static __device__ — no allocation allowed)
__device__ __align__(16) __half g_yh[NN * 16];    // dinv*x padded to 16, fp16
__device__ __align__(16) float  g_aggx[NN * 16];  // aggregated 12-dim fp32 (padded)
__device__ __align__(16) __half g_zh[NN * HID];   // dinv*h1, fp16
__device__ __align__(16) __half g_aggzh[NN * HID];// aggregated z, fp16
__device__ __align__(16) __half g_h2h[NN * HID];  // h2, fp16
__device__ float g_dinv[NN];
__device__ float g_sq[NN];            // sqrt(deg)
__device__ int   g_cnt[NN];
__device__ int   g_rowst[NN + 1];
__device__ int   g_rowcur[NN];
__device__ int   g_csrc[NE];
__device__ int   g_bsum[NB];
__device__ float g_pooled[NG * FCD];

// ---------------------------------------------------------------------------
__global__ void k_init() {
    int i = blockIdx.x * blockDim.x + threadIdx.x;
    if (i < NN) g_cnt[i] = 0;
    if (i < NG * FCD) g_pooled[i] = 0.0f;
}

// in-degree, 4 edges/thread (MLP-4)
__global__ void k_deg(const int* __restrict__ ei) {
    int base = (blockIdx.x * blockDim.x + threadIdx.x) * 4;
    if (base >= NE) return;
    int n = min(4, NE - base);
#pragma unroll
    for (int i = 0; i < 4; i++)
        if (i < n) atomicAdd(&g_cnt[ei[NE + base + i]], 1);
}

// per-block sums of cnt
__global__ void k_scan1() {
    __shared__ int sred[8];
    int b = blockIdx.x, t = threadIdx.x;
    int i = b * 256 + t;
    int v = (i < NN) ? g_cnt[i] : 0;
#pragma unroll
    for (int o = 16; o > 0; o >>= 1) v += __shfl_down_sync(0xffffffffu, v, o);
    if ((t & 31) == 0) sred[t >> 5] = v;
    __syncthreads();
    if (t < 8) {
        int s = sred[t];
#pragma unroll
        for (int o = 4; o > 0; o >>= 1) s += __shfl_down_sync(0xffu, s, o);
        if (t == 0) g_bsum[b] = s;
    }
}

// per-block scan with inline block-offset reduction
__global__ void k_scan3() {
    __shared__ int sred[8];
    __shared__ int swarp[8];
    __shared__ int sboff;
    int b = blockIdx.x, t = threadIdx.x;
    int lane = t & 31, w = t >> 5;

    int s = 0;
    for (int i = t; i < b; i += 256) s += g_bsum[i];
#pragma unroll
    for (int o = 16; o > 0; o >>= 1) s += __shfl_down_sync(0xffffffffu, s, o);
    if (lane == 0) sred[w] = s;
    __syncthreads();
    if (t < 8) {
        int r = sred[t];
#pragma unroll
        for (int o = 4; o > 0; o >>= 1) r += __shfl_down_sync(0xffu, r, o);
        if (t == 0) sboff = r;
    }

    int i = b * 256 + t;
    int v = (i < NN) ? g_cnt[i] : 0;
    int inc = v;
#pragma unroll
    for (int o = 1; o < 32; o <<= 1) {
        int u = __shfl_up_sync(0xffffffffu, inc, o);
        if (lane >= o) inc += u;
    }
    if (lane == 31) swarp[w] = inc;
    __syncthreads();
    if (t < 8) {
        int s2 = swarp[t];
#pragma unroll
        for (int o = 1; o < 8; o <<= 1) {
            int u = __shfl_up_sync(0xffu, s2, o);
            if (t >= o) s2 += u;
        }
        swarp[t] = s2;
    }
    __syncthreads();
    int excl = inc - v + (w ? swarp[w - 1] : 0) + sboff;
    if (i < NN) {
        g_rowst[i]  = excl;
        g_rowcur[i] = excl;
        float deg = (float)(v + 1);
        g_dinv[i] = rsqrtf(deg);
        g_sq[i]   = sqrtf(deg);
    }
    if (b == 0 && t == 0) g_rowst[NN] = NE;
}

// CSR fill, 4 edges/thread
__global__ void k_fill(const int* __restrict__ ei) {
    int base = (blockIdx.x * blockDim.x + threadIdx.x) * 4;
    if (base >= NE) return;
    int s0[4], pos[4];
    int n = min(4, NE - base);
#pragma unroll
    for (int i = 0; i < 4; i++) {
        if (i < n) {
            s0[i] = ei[base + i];
            int d = ei[NE + base + i];
            pos[i] = atomicAdd(&g_rowcur[d], 1);
        }
    }
#pragma unroll
    for (int i = 0; i < 4; i++)
        if (i < n) g_csrc[pos[i]] = s0[i];
}

// y16[node][0..11] = dinv*x fp16, [12..15]=0. 2 lanes/node (8 halves each).
__global__ void k_pre(const float* __restrict__ x) {
    int gid = blockIdx.x * blockDim.x + threadIdx.x;
    int node = gid >> 1;
    if (node >= NN) return;
    int c = gid & 1;
    float d = g_dinv[node];
    uint4 pk;
    if (c == 0) {
        float4 x0 = ((const float4*)x)[node * 3 + 0];
        float4 x1 = ((const float4*)x)[node * 3 + 1];
        __half2 h0 = __floats2half2_rn(x0.x * d, x0.y * d);
        __half2 h1 = __floats2half2_rn(x0.z * d, x0.w * d);
        __half2 h2 = __floats2half2_rn(x1.x * d, x1.y * d);
        __half2 h3 = __floats2half2_rn(x1.z * d, x1.w * d);
        pk.x = *(unsigned*)&h0; pk.y = *(unsigned*)&h1;
        pk.z = *(unsigned*)&h2; pk.w = *(unsigned*)&h3;
    } else {
        float4 x2 = ((const float4*)x)[node * 3 + 2];
        __half2 h0 = __floats2half2_rn(x2.x * d, x2.y * d);
        __half2 h1 = __floats2half2_rn(x2.z * d, x2.w * d);
        pk.x = *(unsigned*)&h0; pk.y = *(unsigned*)&h1;
        pk.z = 0u; pk.w = 0u;
    }
    ((uint4*)g_yh)[node * 2 + c] = pk;
}

// 12-dim fp16 CSR gather, fp32 accumulate. 2 lanes/node. Unroll 8.
__global__ void k_agg12() {
    int gid = blockIdx.x * blockDim.x + threadIdx.x;
    int node = gid >> 1;
    if (node >= NN) return;
    int c = gid & 1;
    int beg = g_rowst[node];
    int end = g_rowst[node + 1];
    const uint4* y = (const uint4*)g_yh;

    float2 a[4];
    {
        uint4 v = y[node * 2 + c];
        const __half2* h = (const __half2*)&v;
#pragma unroll
        for (int i = 0; i < 4; i++) a[i] = __half22float2(h[i]);
    }
    int j = beg;
    for (; j + 8 <= end; j += 8) {
        uint4 v[8];
#pragma unroll
        for (int u = 0; u < 8; u++) v[u] = y[g_csrc[j + u] * 2 + c];
#pragma unroll
        for (int u = 0; u < 8; u++) {
#pragma unroll
            for (int i = 0; i < 4; i++) {
                float2 f = __half22float2(((const __half2*)&v[u])[i]);
                a[i].x += f.x; a[i].y += f.y;
            }
        }
    }
    for (; j < end; j++) {
        uint4 v0 = y[g_csrc[j] * 2 + c];
#pragma unroll
        for (int i = 0; i < 4; i++) {
            float2 f = __half22float2(((const __half2*)&v0)[i]);
            a[i].x += f.x; a[i].y += f.y;
        }
    }
    float4 o0 = make_float4(a[0].x, a[0].y, a[1].x, a[1].y);
    float4 o1 = make_float4(a[2].x, a[2].y, a[3].x, a[3].y);
    ((float4*)g_aggx)[node * 4 + c * 2 + 0] = o0;
    ((float4*)g_aggx)[node * 4 + c * 2 + 1] = o1;
}

// h1 = tanh(dinv*(aggx@W1)+b1); z = dinv*h1 stored fp16. 16 fg/node.
__global__ void k_l1(const float* __restrict__ W1, const float* __restrict__ b1) {
    __shared__ float4 sW[FIN * 16];
    __shared__ float  sb[HID];
    int t = threadIdx.x;
    if (t < FIN * 16) sW[t] = ((const float4*)W1)[t];
    if (t < HID) sb[t] = b1[t];
    __syncthreads();
    int node = blockIdx.x * 16 + (t >> 4);
    if (node >= NN) return;
    int fg = t & 15;
    float4 a0 = ((const float4*)g_aggx)[node * 4 + 0];
    float4 a1 = ((const float4*)g_aggx)[node * 4 + 1];
    float4 a2 = ((const float4*)g_aggx)[node * 4 + 2];
    float av[12] = {a0.x, a0.y, a0.z, a0.w, a1.x, a1.y, a1.z, a1.w,
                    a2.x, a2.y, a2.z, a2.w};
    float4 acc = make_float4(0.f, 0.f, 0.f, 0.f);
#pragma unroll
    for (int k = 0; k < FIN; k++) {
        float4 w = sW[k * 16 + fg];
        float ak = av[k];
        acc.x += ak * w.x; acc.y += ak * w.y; acc.z += ak * w.z; acc.w += ak * w.w;
    }
    float d = g_dinv[node];
    __half2 p0 = __floats2half2_rn(d * tanhf(d * acc.x + sb[fg * 4 + 0]),
                                   d * tanhf(d * acc.y + sb[fg * 4 + 1]));
    __half2 p1 = __floats2half2_rn(d * tanhf(d * acc.z + sb[fg * 4 + 2]),
                                   d * tanhf(d * acc.w + sb[fg * 4 + 3]));
    uint2 pk;
    pk.x = *(unsigned*)&p0;
    pk.y = *(unsigned*)&p1;
    ((uint2*)g_zh)[node * 16 + fg] = pk;
}

// 64-dim fp16 CSR gather, fp32 accumulate, fp16 out. 8 lanes/node. Unroll 8.
__global__ void k_aggz() {
    int gid = blockIdx.x * blockDim.x + threadIdx.x;
    int node = gid >> 3;
    if (node >= NN) return;
    int c = gid & 7;
    int beg = g_rowst[node];
    int end = g_rowst[node + 1];
    const uint4* z = (const uint4*)g_zh;

    float2 a[4];
    {
        uint4 v = z[node * 8 + c];
        const __half2* h = (const __half2*)&v;
#pragma unroll
        for (int i = 0; i < 4; i++) a[i] = __half22float2(h[i]);
    }
    int j = beg;
    for (; j + 8 <= end; j += 8) {
        uint4 v[8];
#pragma unroll
        for (int u = 0; u < 8; u++) v[u] = z[g_csrc[j + u] * 8 + c];
#pragma unroll
        for (int u = 0; u < 8; u++) {
#pragma unroll
            for (int i = 0; i < 4; i++) {
                float2 f = __half22float2(((const __half2*)&v[u])[i]);
                a[i].x += f.x; a[i].y += f.y;
            }
        }
    }
    for (; j < end; j++) {
        uint4 v0 = z[g_csrc[j] * 8 + c];
#pragma unroll
        for (int i = 0; i < 4; i++) {
            float2 f = __half22float2(((const __half2*)&v0)[i]);
            a[i].x += f.x; a[i].y += f.y;
        }
    }
    __half2 o0 = __floats2half2_rn(a[0].x, a[0].y);
    __half2 o1 = __floats2half2_rn(a[1].x, a[1].y);
    __half2 o2 = __floats2half2_rn(a[2].x, a[2].y);
    __half2 o3 = __floats2half2_rn(a[3].x, a[3].y);
    uint4 pk;
    pk.x = *(unsigned*)&o0; pk.y = *(unsigned*)&o1;
    pk.z = *(unsigned*)&o2; pk.w = *(unsigned*)&o3;
    ((uint4*)g_aggzh)[node * 8 + c] = pk;
}

// h2 = tanh(dinv*(aggz@W2)+b2) stored fp16. 32 nodes/block, 128 thr, 4x4 tiles.
__global__ void k_l2(const float* __restrict__ W2, const float* __restrict__ b2) {
    __shared__ float4 sW[HID * 16];      // 16 KB
    __shared__ float  sA[HID * 36];      // 9 KB transposed, pad 36
    __shared__ float  sb[HID];
    int t = threadIdx.x;
    int n0 = blockIdx.x * 32;
    for (int i = t; i < HID * 16; i += 128) sW[i] = ((const float4*)W2)[i];
    if (t < HID) sb[t] = b2[t];
    {
        int n = t >> 2, q = t & 3;   // node 0..31, quarter 0..3 (16 k's each)
#pragma unroll
        for (int h = 0; h < 2; h++) {
            uint4 v = ((const uint4*)g_aggzh)[(n0 + n) * 8 + q * 2 + h];
            int k = q * 16 + h * 8;
#pragma unroll
            for (int i = 0; i < 4; i++) {
                float2 f = __half22float2(((const __half2*)&v)[i]);
                sA[(k + i * 2 + 0) * 36 + n] = f.x;
                sA[(k + i * 2 + 1) * 36 + n] = f.y;
            }
        }
    }
    __syncthreads();
    int fg = t & 15;
    int ng = t >> 4;
    float4 acc[4];
#pragma unroll
    for (int i = 0; i < 4; i++) acc[i] = make_float4(0.f, 0.f, 0.f, 0.f);
#pragma unroll 8
    for (int k = 0; k < HID; k++) {
        float4 w = sW[k * 16 + fg];
        const float4 a = *(const float4*)&sA[k * 36 + ng * 4];
        acc[0].x += a.x * w.x; acc[0].y += a.x * w.y; acc[0].z += a.x * w.z; acc[0].w += a.x * w.w;
        acc[1].x += a.y * w.x; acc[1].y += a.y * w.y; acc[1].z += a.y * w.z; acc[1].w += a.y * w.w;
        acc[2].x += a.z * w.x; acc[2].y += a.z * w.y; acc[2].z += a.z * w.z; acc[2].w += a.z * w.w;
        acc[3].x += a.w * w.x; acc[3].y += a.w * w.y; acc[3].z += a.w * w.z; acc[3].w += a.w * w.w;
    }
    float4 bb = *(const float4*)&sb[fg * 4];
#pragma unroll
    for (int i = 0; i < 4; i++) {
        int node = n0 + ng * 4 + i;
        float d = g_dinv[node];
        __half2 p0 = __floats2half2_rn(tanhf(d * acc[i].x + bb.x),
                                       tanhf(d * acc[i].y + bb.y));
        __half2 p1 = __floats2half2_rn(tanhf(d * acc[i].z + bb.z),
                                       tanhf(d * acc[i].w + bb.w));
        uint2 pk;
        pk.x = *(unsigned*)&p0;
        pk.y = *(unsigned*)&p1;
        ((uint2*)g_h2h)[node * 16 + fg] = pk;
    }
}

// pooling: batch sorted -> block per (graph, split); lane per feature.
__global__ void k_pool(const float* __restrict__ x,
                       const int* __restrict__ batch) {
    int g = blockIdx.x / SPLIT;
    int s = blockIdx.x % SPLIT;
    int f = threadIdx.x;

    int a = 0, b = NN;
    while (a < b) { int m = (a + b) >> 1; if (batch[m] < g) a = m + 1; else b = m; }
    int lo = a;
    a = lo; b = NN;
    while (a < b) { int m = (a + b) >> 1; if (batch[m] < g + 1) a = m + 1; else b = m; }
    int hi = a;

    int cnt = hi - lo;
    int per = (cnt + SPLIT - 1) / SPLIT;
    int st  = lo + s * per;
    int en  = min(st + per, hi);

    if (f < FCD) {
        float acc = 0.0f;
        for (int node = st; node < en; node++) {
            float v;
            if (f < FIN) {
                v = x[node * FIN + f];
            } else if (f < FIN + HID) {
                v = __half2float(g_zh[node * HID + (f - FIN)]) * g_sq[node];
            } else {
                v = __half2float(g_h2h[node * HID + (f - FIN - HID)]);
            }
            acc += v;
        }
        if (st < en) atomicAdd(&g_pooled[g * FCD + f], acc);
    }
}

__global__ void k_fc(const float* __restrict__ fcW,
                     const float* __restrict__ fcb,
                     float* __restrict__ out) {
    __shared__ float sp[FCD];
    int g = blockIdx.x;
    for (int i = threadIdx.x; i < FCD; i += blockDim.x) sp[i] = g_pooled[g * FCD + i];
    __syncthreads();
    int o = threadIdx.x;
    if (o < FCD) {
        const float* wr = fcW + o * FCD;
        float s = fcb[o];
        for (int k = 0; k < FCD; k++) s += sp[k] * wr[k];
        out[g * FCD + o] = s;
    }
}

// ---------------------------------------------------------------------------
extern "C" void kernel_launch(void* const* d_in, const int* in_sizes, int n_in,
                              void* d_out, int out_size) {
    const float* x    = (const float*)d_in[0];
    const float* W1   = (const float*)d_in[1];
    const float* b1   = (const float*)d_in[2];
    const float* W2   = (const float*)d_in[3];
    const float* b2   = (const float*)d_in[4];
    const float* fcW  = (const float*)d_in[5];
    const float* fcb  = (const float*)d_in[6];
    const int*   ei   = (const int*)d_in[7];
    const int*   batch= (const int*)d_in[8];
    float* out = (float*)d_out;
    (void)in_sizes; (void)n_in; (void)out_size;

    k_init <<<(NN + 255) / 256, 256>>>();
    k_deg  <<<(NE / 4 + 255) / 256, 256>>>(ei);
    k_scan1<<<NB, 256>>>();
    k_scan3<<<NB, 256>>>();
    k_fill <<<(NE / 4 + 255) / 256, 256>>>(ei);
    k_pre  <<<(NN * 2 + 255) / 256, 256>>>(x);
    k_agg12<<<(NN * 2 + 255) / 256, 256>>>();
    k_l1   <<<(NN + 15) / 16, 256>>>(W1, b1);
    k_aggz <<<(NN * 8 + 255) / 256, 256>>>();
    k_l2   <<<NN / 32, 128>>>(W2, b2);
    k_pool <<<NG * SPLIT, 160>>>(x, batch);
    k_fc   <<<NG, 160>>>(fcW, fcb, out);
}

// round 10
// speedup vs baseline: 2.8606x; 1.0714x over previous
#include <cuda_runtime.h>
#include <cuda_fp16.h>
#include <math.h>

#define NN 100000
#define NE 1600000
#define NG 256
#define FIN 12
#define HID 64
#define FCD 140
#define SPLIT 8
#define NB 391          // 391*256 = 100096 >= NN

// Scratch (static __device__ — no allocation allowed; zero-init at load)
__device__ __align__(16) __half g_yh[NN * 16];    // dinv*x padded to 16, fp16
__device__ __align__(16) __half g_zh[NN * HID];   // dinv*h1, fp16
__device__ __align__(16) __half g_h2h[NN * HID];  // h2, fp16
__device__ float g_dinv[NN];
__device__ float g_sq[NN];            // sqrt(deg)
__device__ int   g_cnt[NN];           // self-cleaning (zeroed in k_scan3)
__device__ int   g_rowst[NN + 1];
__device__ int   g_rowcur[NN];
__device__ int   g_csrc[NE];
__device__ int   g_bsum[NB];
__device__ float g_pooledp[NG * SPLIT * FCD];  // per-(graph,split) partials

__device__ __forceinline__ float tanha(float x) {
    float r;
    asm("tanh.approx.f32 %0, %1;" : "=f"(r) : "f"(x));
    return r;
}

// ---------------------------------------------------------------------------
// in-degree, 4 edges/thread, int4 loads
__global__ void k_deg(const int* __restrict__ ei) {
    int gid = blockIdx.x * blockDim.x + threadIdx.x;
    if (gid * 4 >= NE) return;
    int4 dv = ((const int4*)(ei + NE))[gid];
    atomicAdd(&g_cnt[dv.x], 1);
    atomicAdd(&g_cnt[dv.y], 1);
    atomicAdd(&g_cnt[dv.z], 1);
    atomicAdd(&g_cnt[dv.w], 1);
}

// per-block sums of cnt
__global__ void k_scan1() {
    __shared__ int sred[8];
    int b = blockIdx.x, t = threadIdx.x;
    int i = b * 256 + t;
    int v = (i < NN) ? g_cnt[i] : 0;
#pragma unroll
    for (int o = 16; o > 0; o >>= 1) v += __shfl_down_sync(0xffffffffu, v, o);
    if ((t & 31) == 0) sred[t >> 5] = v;
    __syncthreads();
    if (t < 8) {
        int s = sred[t];
#pragma unroll
        for (int o = 4; o > 0; o >>= 1) s += __shfl_down_sync(0xffu, s, o);
        if (t == 0) g_bsum[b] = s;
    }
}

// per-block scan with inline block-offset reduction; zeros cnt for next replay
__global__ void k_scan3() {
    __shared__ int sred[8];
    __shared__ int swarp[8];
    __shared__ int sboff;
    int b = blockIdx.x, t = threadIdx.x;
    int lane = t & 31, w = t >> 5;

    int s = 0;
    for (int i = t; i < b; i += 256) s += g_bsum[i];
#pragma unroll
    for (int o = 16; o > 0; o >>= 1) s += __shfl_down_sync(0xffffffffu, s, o);
    if (lane == 0) sred[w] = s;
    __syncthreads();
    if (t < 8) {
        int r = sred[t];
#pragma unroll
        for (int o = 4; o > 0; o >>= 1) r += __shfl_down_sync(0xffu, r, o);
        if (t == 0) sboff = r;
    }

    int i = b * 256 + t;
    int v = (i < NN) ? g_cnt[i] : 0;
    int inc = v;
#pragma unroll
    for (int o = 1; o < 32; o <<= 1) {
        int u = __shfl_up_sync(0xffffffffu, inc, o);
        if (lane >= o) inc += u;
    }
    if (lane == 31) swarp[w] = inc;
    __syncthreads();
    if (t < 8) {
        int s2 = swarp[t];
#pragma unroll
        for (int o = 1; o < 8; o <<= 1) {
            int u = __shfl_up_sync(0xffu, s2, o);
            if (t >= o) s2 += u;
        }
        swarp[t] = s2;
    }
    __syncthreads();
    int excl = inc - v + (w ? swarp[w - 1] : 0) + sboff;
    if (i < NN) {
        g_rowst[i]  = excl;
        g_rowcur[i] = excl;
        g_cnt[i]    = 0;                 // self-clean for next graph replay
        float deg = (float)(v + 1);
        g_dinv[i] = rsqrtf(deg);
        g_sq[i]   = sqrtf(deg);
    }
    if (b == 0 && t == 0) g_rowst[NN] = NE;
}

// fused: CSR fill (blocks [0, FILLB)) + y16 precompute (blocks [FILLB, FILLB+PREB))
#define FILLB 1563   // ceil((NE/4)/256)
#define PREB  782    // ceil((NN*2)/256)
__global__ void k_fillpre(const int* __restrict__ ei, const float* __restrict__ x) {
    if (blockIdx.x < FILLB) {
        int gid = blockIdx.x * blockDim.x + threadIdx.x;
        if (gid * 4 >= NE) return;
        int4 sv = ((const int4*)ei)[gid];
        int4 dv = ((const int4*)(ei + NE))[gid];
        int p0 = atomicAdd(&g_rowcur[dv.x], 1);
        int p1 = atomicAdd(&g_rowcur[dv.y], 1);
        int p2 = atomicAdd(&g_rowcur[dv.z], 1);
        int p3 = atomicAdd(&g_rowcur[dv.w], 1);
        g_csrc[p0] = sv.x;
        g_csrc[p1] = sv.y;
        g_csrc[p2] = sv.z;
        g_csrc[p3] = sv.w;
    } else {
        int gid = (blockIdx.x - FILLB) * blockDim.x + threadIdx.x;
        int node = gid >> 1;
        if (node >= NN) return;
        int c = gid & 1;
        float d = g_dinv[node];
        uint4 pk;
        if (c == 0) {
            float4 x0 = ((const float4*)x)[node * 3 + 0];
            float4 x1 = ((const float4*)x)[node * 3 + 1];
            __half2 h0 = __floats2half2_rn(x0.x * d, x0.y * d);
            __half2 h1 = __floats2half2_rn(x0.z * d, x0.w * d);
            __half2 h2 = __floats2half2_rn(x1.x * d, x1.y * d);
            __half2 h3 = __floats2half2_rn(x1.z * d, x1.w * d);
            pk.x = *(unsigned*)&h0; pk.y = *(unsigned*)&h1;
            pk.z = *(unsigned*)&h2; pk.w = *(unsigned*)&h3;
        } else {
            float4 x2 = ((const float4*)x)[node * 3 + 2];
            __half2 h0 = __floats2half2_rn(x2.x * d, x2.y * d);
            __half2 h1 = __floats2half2_rn(x2.z * d, x2.w * d);
            pk.x = *(unsigned*)&h0; pk.y = *(unsigned*)&h1;
            pk.z = 0u; pk.w = 0u;
        }
        ((uint4*)g_yh)[node * 2 + c] = pk;
    }
}

// fused: 12-dim gather + L1 GEMM. 2 lanes/node, 128 nodes/block (256 thr).
// After gather, lane pair exchanges via shfl_xor(1); each lane computes 32 of
// the 64 outputs: z = dinv*tanh(dinv*(aggx@W1)+b1), stored fp16.
__global__ void k_agg12l1(const float* __restrict__ W1, const float* __restrict__ b1) {
    __shared__ float4 sW[FIN * 16];
    __shared__ float  sb[HID];
    int t = threadIdx.x;
    if (t < FIN * 16) sW[t] = ((const float4*)W1)[t];
    if (t < HID) sb[t] = b1[t];
    __syncthreads();
    int node = blockIdx.x * 128 + (t >> 1);
    int nodec = min(node, NN - 1);        // keep whole warp alive for shuffles
    int c = t & 1;
    int beg = g_rowst[nodec];
    int end = g_rowst[nodec + 1];
    const uint4* y = (const uint4*)g_yh;

    float2 a[4];
    {
        uint4 v = y[nodec * 2 + c];
        const __half2* h = (const __half2*)&v;
#pragma unroll
        for (int i = 0; i < 4; i++) a[i] = __half22float2(h[i]);
    }
    int j = beg;
    for (; j + 8 <= end; j += 8) {
        uint4 v[8];
#pragma unroll
        for (int u = 0; u < 8; u++) v[u] = y[g_csrc[j + u] * 2 + c];
#pragma unroll
        for (int u = 0; u < 8; u++) {
#pragma unroll
            for (int i = 0; i < 4; i++) {
                float2 f = __half22float2(((const __half2*)&v[u])[i]);
                a[i].x += f.x; a[i].y += f.y;
            }
        }
    }
    for (; j < end; j++) {
        uint4 v0 = y[g_csrc[j] * 2 + c];
#pragma unroll
        for (int i = 0; i < 4; i++) {
            float2 f = __half22float2(((const __half2*)&v0)[i]);
            a[i].x += f.x; a[i].y += f.y;
        }
    }
    // exchange with pair lane: obtain partner's 8 floats
    float p[8];
#pragma unroll
    for (int i = 0; i < 4; i++) {
        p[i * 2 + 0] = __shfl_xor_sync(0xffffffffu, a[i].x, 1);
        p[i * 2 + 1] = __shfl_xor_sync(0xffffffffu, a[i].y, 1);
    }
    float kv[FIN];
    if (c == 0) {
        kv[0] = a[0].x; kv[1] = a[0].y; kv[2] = a[1].x; kv[3] = a[1].y;
        kv[4] = a[2].x; kv[5] = a[2].y; kv[6] = a[3].x; kv[7] = a[3].y;
        kv[8] = p[0];   kv[9] = p[1];   kv[10] = p[2];  kv[11] = p[3];
    } else {
        kv[0] = p[0]; kv[1] = p[1]; kv[2] = p[2]; kv[3] = p[3];
        kv[4] = p[4]; kv[5] = p[5]; kv[6] = p[6]; kv[7] = p[7];
        kv[8] = a[0].x; kv[9] = a[0].y; kv[10] = a[1].x; kv[11] = a[1].y;
    }
    // 12 -> 32 outputs (features c*32 .. c*32+31)
    float4 acc[8];
#pragma unroll
    for (int i = 0; i < 8; i++) acc[i] = make_float4(0.f, 0.f, 0.f, 0.f);
#pragma unroll
    for (int k = 0; k < FIN; k++) {
        float ak = kv[k];
#pragma unroll
        for (int i = 0; i < 8; i++) {
            float4 w = sW[k * 16 + c * 8 + i];
            acc[i].x += ak * w.x; acc[i].y += ak * w.y;
            acc[i].z += ak * w.z; acc[i].w += ak * w.w;
        }
    }
    if (node < NN) {
        float d = g_dinv[nodec];
#pragma unroll
        for (int i = 0; i < 4; i++) {
            float4 u0 = acc[i * 2], u1 = acc[i * 2 + 1];
            const float* bp = &sb[c * 32 + i * 8];
            __half2 q0 = __floats2half2_rn(d * tanha(d * u0.x + bp[0]),
                                           d * tanha(d * u0.y + bp[1]));
            __half2 q1 = __floats2half2_rn(d * tanha(d * u0.z + bp[2]),
                                           d * tanha(d * u0.w + bp[3]));
            __half2 q2 = __floats2half2_rn(d * tanha(d * u1.x + bp[4]),
                                           d * tanha(d * u1.y + bp[5]));
            __half2 q3 = __floats2half2_rn(d * tanha(d * u1.z + bp[6]),
                                           d * tanha(d * u1.w + bp[7]));
            uint4 pk;
            pk.x = *(unsigned*)&q0; pk.y = *(unsigned*)&q1;
            pk.z = *(unsigned*)&q2; pk.w = *(unsigned*)&q3;
            ((uint4*)g_zh)[nodec * 8 + c * 4 + i] = pk;
        }
    }
}

// fused: 64-dim gather straight into transposed smem tile + L2 GEMM.
// 32 nodes/block, 128 threads. h2 = tanh(dinv*(aggz@W2)+b2), fp16.
__global__ void k_aggzl2(const float* __restrict__ W2, const float* __restrict__ b2) {
    __shared__ float4 sW[HID * 16];      // 16 KB
    __shared__ float  sA[HID * 36];      // 9 KB transposed aggz, pad 36
    __shared__ float  sb[HID];
    int t = threadIdx.x;
    int n0 = blockIdx.x * 32;
    for (int i = t; i < HID * 16; i += 128) sW[i] = ((const float4*)W2)[i];
    if (t < HID) sb[t] = b2[t];

    const uint4* z = (const uint4*)g_zh;
    int c = t & 7;
#pragma unroll
    for (int p = 0; p < 2; p++) {
        int n = (t >> 3) + p * 16;       // local node 0..31
        int node = n0 + n;
        int beg = g_rowst[node];
        int end = g_rowst[node + 1];
        float2 a[4];
        {
            uint4 v = z[node * 8 + c];
            const __half2* h = (const __half2*)&v;
#pragma unroll
            for (int i = 0; i < 4; i++) a[i] = __half22float2(h[i]);
        }
        int j = beg;
        for (; j + 8 <= end; j += 8) {
            uint4 v[8];
#pragma unroll
            for (int u = 0; u < 8; u++) v[u] = z[g_csrc[j + u] * 8 + c];
#pragma unroll
            for (int u = 0; u < 8; u++) {
#pragma unroll
                for (int i = 0; i < 4; i++) {
                    float2 f = __half22float2(((const __half2*)&v[u])[i]);
                    a[i].x += f.x; a[i].y += f.y;
                }
            }
        }
        for (; j < end; j++) {
            uint4 v0 = z[g_csrc[j] * 8 + c];
#pragma unroll
            for (int i = 0; i < 4; i++) {
                float2 f = __half22float2(((const __half2*)&v0)[i]);
                a[i].x += f.x; a[i].y += f.y;
            }
        }
#pragma unroll
        for (int i = 0; i < 4; i++) {
            int k = c * 8 + i * 2;
            sA[(k + 0) * 36 + n] = a[i].x;
            sA[(k + 1) * 36 + n] = a[i].y;
        }
    }
    __syncthreads();

    int fg = t & 15;
    int ng = t >> 4;
    float4 acc[4];
#pragma unroll
    for (int i = 0; i < 4; i++) acc[i] = make_float4(0.f, 0.f, 0.f, 0.f);
#pragma unroll 8
    for (int k = 0; k < HID; k++) {
        float4 w = sW[k * 16 + fg];
        const float4 a = *(const float4*)&sA[k * 36 + ng * 4];
        acc[0].x += a.x * w.x; acc[0].y += a.x * w.y; acc[0].z += a.x * w.z; acc[0].w += a.x * w.w;
        acc[1].x += a.y * w.x; acc[1].y += a.y * w.y; acc[1].z += a.y * w.z; acc[1].w += a.y * w.w;
        acc[2].x += a.z * w.x; acc[2].y += a.z * w.y; acc[2].z += a.z * w.z; acc[2].w += a.z * w.w;
        acc[3].x += a.w * w.x; acc[3].y += a.w * w.y; acc[3].z += a.w * w.z; acc[3].w += a.w * w.w;
    }
    float4 bb = *(const float4*)&sb[fg * 4];
#pragma unroll
    for (int i = 0; i < 4; i++) {
        int node = n0 + ng * 4 + i;
        float d = g_dinv[node];
        __half2 p0 = __floats2half2_rn(tanha(d * acc[i].x + bb.x),
                                       tanha(d * acc[i].y + bb.y));
        __half2 p1 = __floats2half2_rn(tanha(d * acc[i].z + bb.z),
                                       tanha(d * acc[i].w + bb.w));
        uint2 pk;
        pk.x = *(unsigned*)&p0;
        pk.y = *(unsigned*)&p1;
        ((uint2*)g_h2h)[node * 16 + fg] = pk;
    }
}

// pooling: atomic-free; write per-(graph,split) partials.
__global__ void k_pool(const float* __restrict__ x,
                       const int* __restrict__ batch) {
    int g = blockIdx.x / SPLIT;
    int s = blockIdx.x % SPLIT;
    int f = threadIdx.x;

    int a = 0, b = NN;
    while (a < b) { int m = (a + b) >> 1; if (batch[m] < g) a = m + 1; else b = m; }
    int lo = a;
    a = lo; b = NN;
    while (a < b) { int m = (a + b) >> 1; if (batch[m] < g + 1) a = m + 1; else b = m; }
    int hi = a;

    int cnt = hi - lo;
    int per = (cnt + SPLIT - 1) / SPLIT;
    int st  = lo + s * per;
    int en  = min(st + per, hi);

    if (f < FCD) {
        float acc = 0.0f;
        for (int node = st; node < en; node++) {
            float v;
            if (f < FIN) {
                v = x[node * FIN + f];
            } else if (f < FIN + HID) {
                v = __half2float(g_zh[node * HID + (f - FIN)]) * g_sq[node];
            } else {
                v = __half2float(g_h2h[node * HID + (f - FIN - HID)]);
            }
            acc += v;
        }
        g_pooledp[(g * SPLIT + s) * FCD + f] = acc;   // unconditional (0 if empty)
    }
}

__global__ void k_fc(const float* __restrict__ fcW,
                     const float* __restrict__ fcb,
                     float* __restrict__ out) {
    __shared__ float sp[FCD];
    int g = blockIdx.x;
    for (int i = threadIdx.x; i < FCD; i += blockDim.x) {
        float s = 0.0f;
#pragma unroll
        for (int q = 0; q < SPLIT; q++)
            s += g_pooledp[(g * SPLIT + q) * FCD + i];
        sp[i] = s;
    }
    __syncthreads();
    int o = threadIdx.x;
    if (o < FCD) {
        const float* wr = fcW + o * FCD;
        float s = fcb[o];
        for (int k = 0; k < FCD; k++) s += sp[k] * wr[k];
        out[g * FCD + o] = s;
    }
}

// ---------------------------------------------------------------------------
extern "C" void kernel_launch(void* const* d_in, const int* in_sizes, int n_in,
                              void* d_out, int out_size) {
    const float* x    = (const float*)d_in[0];
    const float* W1   = (const float*)d_in[1];
    const float* b1   = (const float*)d_in[2];
    const float* W2   = (const float*)d_in[3];
    const float* b2   = (const float*)d_in[4];
    const float* fcW  = (const float*)d_in[5];
    const float* fcb  = (const float*)d_in[6];
    const int*   ei   = (const int*)d_in[7];
    const int*   batch= (const int*)d_in[8];
    float* out = (float*)d_out;
    (void)in_sizes; (void)n_in; (void)out_size;

    k_deg     <<<(NE / 4 + 255) / 256, 256>>>(ei);
    k_scan1   <<<NB, 256>>>();
    k_scan3   <<<NB, 256>>>();
    k_fillpre <<<FILLB + PREB, 256>>>(ei, x);
    k_agg12l1 <<<(NN + 127) / 128, 256>>>(W1, b1);
    k_aggzl2  <<<NN / 32, 128>>>(W2, b2);
    k_pool    <<<NG * SPLIT, 160>>>(x, batch);
    k_fc      <<<NG, 160>>>(fcW, fcb, out);
}